// round 10
// baseline (speedup 1.0000x reference)
#include <cuda_runtime.h>
#include <cuda_fp16.h>
#include <cuda_bf16.h>

#define BS    32
#define NTOK  512
#define A2LEN 150
#define NTOT  (BS*NTOK)          // 16384
#define NDR   (BS*A2LEN)         // 4800 = 75*64
#define YW    128                // compact y width (120 used + 8 pad)

// ---------------- scratch ----------------------------------------------------
__device__ float g_y  [NTOT * YW];
__device__ float g_yd [3 * NDR * 24];
__device__ float g_sp [NTOT * 40];
__device__ float g_dn [NDR * 24];
__device__ int   g_inv[NTOK];
__device__ int   g_src[2 * NTOK * 32];    // [i][r][t]
__device__ __nv_bfloat16 g_xh[NTOT * 96]; // bf16 x
__device__ __nv_bfloat16 g_wh[208 * 96];  // bf16 W rows: [0,128)=qkv compact, [128,208)=dense
__device__ float g_bias[208];

// ---------------- f32x2 helpers ----------------------------------------------
__device__ __forceinline__ void ffma2(unsigned long long& d,
                                      unsigned long long a,
                                      unsigned long long b) {
    asm("fma.rn.f32x2 %0, %1, %2, %0;" : "+l"(d) : "l"(a), "l"(b));
}
__device__ __forceinline__ unsigned long long bcast2(float v) {
    unsigned long long r; unsigned int u = __float_as_uint(v);
    asm("mov.b64 %0, {%1, %1};" : "=l"(r) : "r"(u));
    return r;
}
__device__ __forceinline__ unsigned long long addf2(unsigned long long a,
                                                    unsigned long long b) {
    unsigned long long r;
    asm("add.rn.f32x2 %0, %1, %2;" : "=l"(r) : "l"(a), "l"(b));
    return r;
}

__device__ __forceinline__ int rowmap(int o) {
    if (o < 40)  return 32 + o;
    if (o < 80)  return 88 + o;
    if (o < 120) return 144 + o;
    return 32;
}
__device__ __forceinline__ int rowmap_all(int o) {   // 0..207 -> Wqv row
    if (o < 128) return rowmap(o);
    int oo = o - 128; if (oo > 71) oo = 71;
    int p = oo / 24, c = oo - p*24;
    return 96*p + 72 + c;
}

// bf16 m16n8k16 MMA, fp32 accumulate
__device__ __forceinline__ void mma16816(float* c,
                                         unsigned a0, unsigned a1,
                                         unsigned a2, unsigned a3,
                                         unsigned b0, unsigned b1) {
    asm volatile(
        "mma.sync.aligned.m16n8k16.row.col.f32.bf16.bf16.f32 "
        "{%0,%1,%2,%3}, {%4,%5,%6,%7}, {%8,%9}, {%0,%1,%2,%3};"
        : "+f"(c[0]), "+f"(c[1]), "+f"(c[2]), "+f"(c[3])
        : "r"(a0), "r"(a1), "r"(a2), "r"(a3), "r"(b0), "r"(b1));
}

#define XS 104    // bf16 smem row stride

// =============== Kernel 0: bf16 conversions + coo transpose + inv =============
// grid 257: [0,192) x conv; 192: W conv + bias + inv; [193,257): coo transpose
__global__ void __launch_bounds__(256) k_pre(const float* __restrict__ x,
                                             const float* __restrict__ W,
                                             const int* __restrict__ coo0,
                                             const int* __restrict__ coo1,
                                             const int* __restrict__ a2a) {
    const int blk = blockIdx.x, tid = threadIdx.x;
    if (blk < 192) {
        const int base = blk*4096 + tid;        // 786432 half2 total
#pragma unroll
        for (int j = 0; j < 16; j++) {
            int idx = base + j*256;
            float2 v = *(const float2*)&x[idx*2];
            *(__nv_bfloat162*)&g_xh[idx*2] = __float22bfloat162_rn(v);
        }
    } else if (blk == 192) {
        for (int i = tid; i < 208*96; i += 256) {
            int o = i / 96, k = i - o*96;
            g_wh[i] = __float2bfloat16_rn(W[rowmap_all(o)*97 + k]);
        }
        if (tid < 208) g_bias[tid] = W[rowmap_all(tid)*97 + 96];
        g_inv[tid] = -1; g_inv[tid + 256] = -1;
        __syncthreads();
        if (tid < A2LEN) g_inv[a2a[tid]] = tid;
    } else {
        const int pb = blk - 193;               // 0..63
#pragma unroll
        for (int j = 0; j < 2; j++) {
            int g = pb*512 + j*256 + tid;
            int i = g >> 14;
            int e = g & 16383;
            const int* coo = i ? coo1 : coo0;
            int src = coo[e*3 + 1];
            int tok = e >> 5, r = e & 31;
            g_src[i*16384 + r*512 + tok] = src;
        }
    }
}

// =============== Kernel A: GEMMs (587 blocks, 256 thr) ========================
// blocks [0,512):   qkv bf16 MMA, tile 32 tok x 128 out
// blocks [512,587): dense-head qkv bf16 MMA, tile 64 rows x 72(+8) out
__global__ void __launch_bounds__(256, 4) k_gemms(const int* __restrict__ a2a) {
    extern __shared__ __align__(16) float sm[];
    const int blk = blockIdx.x;
    const int tid = threadIdx.x;

    if (blk < 512) {
        __nv_bfloat16* sX  = (__nv_bfloat16*)sm;     // [32][XS]
        __nv_bfloat16* sWh = sX + 32*XS;             // [128][XS]
        float*         sB  = (float*)(sWh + 128*XS); // [128]
        const int t0 = blk * 32;

        for (int idx = tid; idx < 384; idx += 256) {          // X: 32 rows x 12 uint4
            int row = idx / 12, q = idx - row*12;
            *(uint4*)&sX[row*XS + q*8] =
                *(const uint4*)&g_xh[(t0 + row)*96 + q*8];
        }
        for (int idx = tid; idx < 1536; idx += 256) {         // W: 128 rows x 12 uint4
            int row = idx / 12, q = idx - row*12;
            *(uint4*)&sWh[row*XS + q*8] =
                *(const uint4*)&g_wh[row*96 + q*8];
        }
        if (tid < 128) sB[tid] = g_bias[tid];
        __syncthreads();

        const int warp = tid >> 5, lane = tid & 31;
        const int mw = (warp & 1) * 16;      // 2 m-warps
        const int nw = (warp >> 1) * 32;     // 4 n-warps
        const int gr = lane >> 2;
        const int qp = (lane & 3) * 2;

        float acc[4][4];
#pragma unroll
        for (int n = 0; n < 4; n++)
#pragma unroll
            for (int j = 0; j < 4; j++) acc[n][j] = 0.f;

        const __nv_bfloat16* ab = &sX[(mw + gr)*XS + qp];
#pragma unroll
        for (int ks = 0; ks < 6; ks++) {
            const int k0 = ks * 16;
            unsigned a0 = *(const unsigned*)(ab + k0);
            unsigned a1 = *(const unsigned*)(ab + k0 + 8*XS);
            unsigned a2 = *(const unsigned*)(ab + k0 + 8);
            unsigned a3 = *(const unsigned*)(ab + k0 + 8*XS + 8);
#pragma unroll
            for (int n = 0; n < 4; n++) {
                const __nv_bfloat16* bb = &sWh[(nw + n*8 + gr)*XS + k0 + qp];
                unsigned b0 = *(const unsigned*)bb;
                unsigned b1 = *(const unsigned*)(bb + 8);
                mma16816(acc[n], a0, a1, a2, a3, b0, b1);
            }
        }
        const int r0 = t0 + mw + gr;
#pragma unroll
        for (int n = 0; n < 4; n++) {
            int col = nw + n*8 + qp;
            float bb0 = sB[col], bb1 = sB[col + 1];
            *(float2*)&g_y[r0*YW + col] =
                make_float2(acc[n][0] + bb0, acc[n][1] + bb1);
            *(float2*)&g_y[(r0 + 8)*YW + col] =
                make_float2(acc[n][2] + bb0, acc[n][3] + bb1);
        }
    } else {
        // dense-head qkv: 64 a2a-rows x 80 outputs (72 real)
        const int d = blk - 512;                     // 0..74
        __nv_bfloat16* sX  = (__nv_bfloat16*)sm;     // [64][XS]
        __nv_bfloat16* sWh = sX + 64*XS;             // [80][XS]
        float*         sB  = (float*)(sWh + 80*XS);  // [80]
        int*           sRow = (int*)(sB + 80);       // [64]
        const int r0 = d * 64;

        if (tid < 64) {
            int r = r0 + tid;
            int b = r / A2LEN, dd = r - b*A2LEN;
            sRow[tid] = b*NTOK + a2a[dd];
        }
        __syncthreads();
        for (int idx = tid; idx < 768; idx += 256) {          // X: 64 x 12 uint4
            int row = idx / 12, q = idx - row*12;
            *(uint4*)&sX[row*XS + q*8] =
                *(const uint4*)&g_xh[sRow[row]*96 + q*8];
        }
        for (int idx = tid; idx < 960; idx += 256) {          // W: 80 x 12 uint4
            int row = idx / 12, q = idx - row*12;
            *(uint4*)&sWh[row*XS + q*8] =
                *(const uint4*)&g_wh[(128 + row)*96 + q*8];
        }
        if (tid < 80) sB[tid] = g_bias[128 + tid];
        __syncthreads();

        const int warp = tid >> 5, lane = tid & 31;
        const int mw = (warp & 3) * 16;
        const int nw = (warp >> 2) * 40;
        const int gr = lane >> 2;
        const int qp = (lane & 3) * 2;

        float acc[5][4];
#pragma unroll
        for (int n = 0; n < 5; n++)
#pragma unroll
            for (int j = 0; j < 4; j++) acc[n][j] = 0.f;

        const __nv_bfloat16* ab = &sX[(mw + gr)*XS + qp];
#pragma unroll
        for (int ks = 0; ks < 6; ks++) {
            const int k0 = ks * 16;
            unsigned a0 = *(const unsigned*)(ab + k0);
            unsigned a1 = *(const unsigned*)(ab + k0 + 8*XS);
            unsigned a2 = *(const unsigned*)(ab + k0 + 8);
            unsigned a3 = *(const unsigned*)(ab + k0 + 8*XS + 8);
#pragma unroll
            for (int n = 0; n < 5; n++) {
                const __nv_bfloat16* bb = &sWh[(nw + n*8 + gr)*XS + k0 + qp];
                unsigned b0 = *(const unsigned*)bb;
                unsigned b1 = *(const unsigned*)(bb + 8);
                mma16816(acc[n], a0, a1, a2, a3, b0, b1);
            }
        }
        const int rr = r0 + mw + gr;
#pragma unroll
        for (int n = 0; n < 5; n++) {
            int col = nw + n*8 + qp;
            if (col < 72) {                          // pairs never straddle planes
                int p = col / 24, c = col - p*24;
                float bb0 = sB[col], bb1 = sB[col + 1];
                *(float2*)&g_yd[p*(NDR*24) + rr*24 + c] =
                    make_float2(acc[n][0] + bb0, acc[n][1] + bb1);
                *(float2*)&g_yd[p*(NDR*24) + (rr + 8)*24 + c] =
                    make_float2(acc[n][2] + bb0, acc[n][3] + bb1);
            }
        }
    }
}

// =============== Kernel B: both attentions (352 blocks, 256 thr) ==============
#define SPLH (NTOK*12)           // halves per (plane,hp) = 6144 (12 KB)
__global__ void __launch_bounds__(256) k_attn() {
    extern __shared__ __align__(16) float smf[];
    const int blk = blockIdx.x;
    const int tid = threadIdx.x;

    if (blk < 256) {
        __half* hs = (__half*)smf;               // 48 KB
        const int b    = blk >> 3;
        const int i    = (blk >> 2) & 1;
        const int quar = blk & 3;

        for (int idx = tid; idx < 10240; idx += 256) {
            int p    = idx / 5120;
            int rem  = idx - p*5120;
            int hp   = rem / 2560;
            int rem2 = rem - hp*2560;
            int tok  = rem2 / 5;
            int c    = rem2 - tok*5;
            float2 v = *(const float2*)&g_y[(b*NTOK + tok)*YW + 40 + p*40 + i*20 + hp*10 + 2*c];
            *(__half2*)&hs[(p*2 + hp)*SPLH + tok*12 + 2*c] = __float22half2_rn(v);
        }
        __syncthreads();

        const int t  = quar*128 + (tid >> 1);
        const int hp = tid & 1;
        const __half* sK = hs + hp*SPLH;
        const __half* sV = hs + (2 + hp)*SPLH;
        const float* qp = &g_y[(b*NTOK + t)*YW + i*20 + hp*10];
        __half2 qh[5];
#pragma unroll
        for (int w = 0; w < 5; w++)
            qh[w] = __floats2half2_rn(qp[2*w], qp[2*w+1]);
        const int* srcp = &g_src[i*16384 + t];
        const float scale = 0.44721359549995793f;   // 1/sqrt(5)
        float l0 = 0.f, l1 = 0.f;
        __half2 acc0 = __float2half2_rn(0.f), acc1 = acc0, acc2 = acc0,
                acc3 = acc0, acc4 = acc0;
#pragma unroll 4
        for (int r = 0; r < 32; r++) {
            int base = srcp[r*512] * 12;
            uint2 ka = *(const uint2*)&sK[base];
            uint2 kb = *(const uint2*)&sK[base + 4];
            unsigned int kc = *(const unsigned int*)&sK[base + 8];
            __half2 d0 = __habs2(__hsub2(qh[0], *(const __half2*)&ka.x));
            __half2 d1 = __habs2(__hsub2(qh[1], *(const __half2*)&ka.y));
            __half2 d2 = __habs2(__hsub2(qh[2], *(const __half2*)&kb.x));
            __half2 d3 = __habs2(__hsub2(qh[3], *(const __half2*)&kb.y));
            __half2 d4 = __habs2(__hsub2(qh[4], *(const __half2*)&kc));
            __half2 u = __hadd2(d0, d1);             // (A,A)
            __half2 v = __hadd2(d3, d4);             // (B,B)
            __half2 uv = __hadd2(__halves2half2(__low2half(u),  __low2half(v)),
                                 __halves2half2(__high2half(u), __high2half(v)));
            __half2 s2 = __hadd2(uv, d2);            // (sumA, sumB)
            float2 sf = __half22float2(s2);
            float p0 = __expf(-sf.x * scale);
            float p1 = __expf(-sf.y * scale);
            l0 += p0; l1 += p1;
            __half h0 = __float2half_rn(p0), h1 = __float2half_rn(p1);
            __half2 pp00 = __halves2half2(h0, h0);
            __half2 pp01 = __halves2half2(h0, h1);
            __half2 pp11 = __halves2half2(h1, h1);
            uint2 va = *(const uint2*)&sV[base];
            uint2 vb = *(const uint2*)&sV[base + 4];
            unsigned int vc = *(const unsigned int*)&sV[base + 8];
            acc0 = __hfma2(pp00, *(const __half2*)&va.x, acc0);
            acc1 = __hfma2(pp00, *(const __half2*)&va.y, acc1);
            acc2 = __hfma2(pp01, *(const __half2*)&vb.x, acc2);
            acc3 = __hfma2(pp11, *(const __half2*)&vb.y, acc3);
            acc4 = __hfma2(pp11, *(const __half2*)&vc,   acc4);
        }
        float inv0 = 1.0f / l0, inv1 = 1.0f / l1;
        float2 f0 = __half22float2(acc0);
        float2 f1 = __half22float2(acc1);
        float2 f2 = __half22float2(acc2);
        float2 f3 = __half22float2(acc3);
        float2 f4 = __half22float2(acc4);
        float* op = &g_sp[(b*NTOK + t)*40 + i*20 + hp*10];
        *(float2*)&op[0] = make_float2(f0.x*inv0, f0.y*inv0);
        *(float2*)&op[2] = make_float2(f1.x*inv0, f1.y*inv0);
        *(float2*)&op[4] = make_float2(f2.x*inv0, f2.y*inv1);
        *(float2*)&op[6] = make_float2(f3.x*inv1, f3.y*inv1);
        *(float2*)&op[8] = make_float2(f4.x*inv1, f4.y*inv1);
    } else {
        const int idx = blk - 256;               // 0..95
        const int b     = idx & 31;
        const int d0    = (idx >> 5) * 64;       // 0,64,128
        float* sK = smf;                         // 150*24
        float* sV = smf + A2LEN*24;
        const int P = NDR * 24;
        for (int j = tid; j < A2LEN*24; j += 256) {
            sK[j] = g_yd[P   + b*A2LEN*24 + j];
            sV[j] = g_yd[2*P + b*A2LEN*24 + j];
        }
        __syncthreads();
        const int dl = tid >> 2, h = tid & 3;
        const int d = d0 + dl;
        if (d >= A2LEN) return;
        const float* qp = &g_yd[(b*A2LEN + d)*24 + h*6];
        float q[6];
#pragma unroll
        for (int w = 0; w < 6; w++) q[w] = qp[w];
        const float scale = 0.4082482904638631f;    // 1/sqrt(6)
        float l = 0.f;
        float acc[6] = {0.f,0.f,0.f,0.f,0.f,0.f};
#pragma unroll 2
        for (int s = 0; s < A2LEN; s++) {
            const float* kp = &sK[s*24 + h*6];
            float2 ka = *(const float2*)kp;
            float2 kb = *(const float2*)(kp + 2);
            float2 kc = *(const float2*)(kp + 4);
            float ds = fabsf(q[0]-ka.x) + fabsf(q[1]-ka.y) + fabsf(q[2]-kb.x)
                     + fabsf(q[3]-kb.y) + fabsf(q[4]-kc.x) + fabsf(q[5]-kc.y);
            float p = __expf(-ds * scale);
            l += p;
            const float* vp = &sV[s*24 + h*6];
            float2 va = *(const float2*)vp;
            float2 vb = *(const float2*)(vp + 2);
            float2 vc = *(const float2*)(vp + 4);
            acc[0] += p*va.x; acc[1] += p*va.y; acc[2] += p*vb.x;
            acc[3] += p*vb.y; acc[4] += p*vc.x; acc[5] += p*vc.y;
        }
        {   // zero-pad key: denominator only
            float ds = fabsf(q[0]) + fabsf(q[1]) + fabsf(q[2])
                     + fabsf(q[3]) + fabsf(q[4]) + fabsf(q[5]);
            l += __expf(-ds * scale);
        }
        float inv = 1.0f / l;
        float* op = &g_dn[(b*A2LEN + d)*24 + h*6];
#pragma unroll
        for (int w = 0; w < 6; w++) op[w] = acc[w]*inv;
    }
}

// =============== Kernel C: out = x + SiLU(b) @ Wf^T + bias =====================
__global__ void __launch_bounds__(256) k_final(const float* __restrict__ x,
                                               const float* __restrict__ Wf,
                                               float* __restrict__ out) {
    __shared__ __align__(16) float sY[64*65];
    __shared__ __align__(16) float sW[64*98];
    __shared__ __align__(16) float sB[96];
    const int t0 = blockIdx.x * 64;
    const int tid = threadIdx.x;

    for (int idx = tid; idx < 64*96; idx += 256) {
        int o = idx / 64, c = idx - o*64;
        sW[c*98 + o] = Wf[o*97 + 32 + c];
    }
    if (tid < 96) sB[tid] = Wf[tid*97 + 96];
    for (int idx = tid; idx < 64*64; idx += 256) {
        int c = idx >> 6, t = idx & 63;
        int tt = t0 + t;
        float v;
        if (c < 40) {
            v = g_sp[tt*40 + c];
        } else {
            int b = tt >> 9, tok = tt & 511;
            int d = g_inv[tok];
            v = (d >= 0) ? g_dn[(b*A2LEN + d)*24 + (c - 40)] : 0.f;
        }
        float sg = 1.0f / (1.0f + __expf(-1.702f * v));
        sY[t*65 + c] = v * sg;
    }
    __syncthreads();

    const int tb = (tid & 15) * 4;
    const int ob = (tid >> 4) * 6;
    unsigned long long acc[4][3];
#pragma unroll
    for (int j = 0; j < 3; j++) {
        unsigned long long bv = *(const unsigned long long*)&sB[ob + 2*j];
        acc[0][j] = bv; acc[1][j] = bv; acc[2][j] = bv; acc[3][j] = bv;
    }
#pragma unroll 4
    for (int k = 0; k < 64; k++) {
        unsigned long long w0 = *(const unsigned long long*)&sW[k*98 + ob];
        unsigned long long w1 = *(const unsigned long long*)&sW[k*98 + ob + 2];
        unsigned long long w2 = *(const unsigned long long*)&sW[k*98 + ob + 4];
#pragma unroll
        for (int t = 0; t < 4; t++) {
            unsigned long long yv = bcast2(sY[(tb + t)*65 + k]);
            ffma2(acc[t][0], yv, w0);
            ffma2(acc[t][1], yv, w1);
            ffma2(acc[t][2], yv, w2);
        }
    }
#pragma unroll
    for (int t = 0; t < 4; t++) {
        int tt = t0 + tb + t;
#pragma unroll
        for (int j = 0; j < 3; j++) {
            unsigned long long xv = *(const unsigned long long*)&x[tt*96 + ob + 2*j];
            *(unsigned long long*)&out[tt*96 + ob + 2*j] = addf2(acc[t][j], xv);
        }
    }
}

// ---------------- launch -------------------------------------------------------
extern "C" void kernel_launch(void* const* d_in, const int* in_sizes, int n_in,
                              void* d_out, int out_size) {
    const float* x    = (const float*)d_in[0];
    const float* wqv  = (const float*)d_in[1];
    const float* wf   = (const float*)d_in[2];
    const int*   coo0 = (const int*)d_in[3];
    const int*   coo1 = (const int*)d_in[4];
    const int*   a2a  = (const int*)d_in[5];
    float*       out  = (float*)d_out;
    (void)in_sizes; (void)n_in; (void)out_size;

    // qkv branch: (32+128)*XS*2 + 128*4 = 33792 ; dense branch: 30528
    const int smemA = (32*XS + 128*XS) * 2 + 128 * 4;        // 33792
    const int smemB = 4 * SPLH * sizeof(__half);             // 49152
    static int inited = 0;
    if (!inited) {
        cudaFuncSetAttribute(k_gemms, cudaFuncAttributeMaxDynamicSharedMemorySize, smemA);
        cudaFuncSetAttribute(k_attn,  cudaFuncAttributeMaxDynamicSharedMemorySize, smemB);
        inited = 1;
    }

    k_pre  <<<257, 256>>>(x, wqv, coo0, coo1, a2a);
    k_gemms<<<587, 256, smemA>>>(a2a);
    k_attn <<<352, 256, smemB>>>();
    k_final<<<256, 256>>>(x, wf, out);
}

// round 11
// speedup vs baseline: 1.1326x; 1.1326x over previous
#include <cuda_runtime.h>
#include <cuda_fp16.h>
#include <cuda_bf16.h>

#define BS    32
#define NTOK  512
#define A2LEN 150
#define NTOT  (BS*NTOK)          // 16384
#define NDR   (BS*A2LEN)         // 4800 = 75*64
#define YW    128                // compact y width (120 used + 8 pad)

// ---------------- scratch ----------------------------------------------------
__device__ float g_y  [NTOT * YW];
__device__ float g_yd [3 * NDR * 24];
__device__ float g_sp [NTOT * 40];
__device__ float g_dn [NDR * 24];
__device__ int   g_inv[NTOK];
__device__ int   g_src[2 * NTOK * 32];    // [i][r][t]
__device__ __nv_bfloat16 g_xh[NTOT * 96]; // bf16 x
__device__ __nv_bfloat16 g_wh[208 * 96];  // bf16 Wqv rows: [0,128) compact, [128,208) dense
__device__ __nv_bfloat16 g_wf[96 * 64];   // bf16 fanout W (cols 32..96)
__device__ float g_bias[208];

// ---------------- f32x2 helpers ----------------------------------------------
__device__ __forceinline__ unsigned long long addf2(unsigned long long a,
                                                    unsigned long long b) {
    unsigned long long r;
    asm("add.rn.f32x2 %0, %1, %2;" : "=l"(r) : "l"(a), "l"(b));
    return r;
}

__device__ __forceinline__ int rowmap(int o) {
    if (o < 40)  return 32 + o;
    if (o < 80)  return 88 + o;
    if (o < 120) return 144 + o;
    return 32;
}
__device__ __forceinline__ int rowmap_all(int o) {   // 0..207 -> Wqv row
    if (o < 128) return rowmap(o);
    int oo = o - 128; if (oo > 71) oo = 71;
    int p = oo / 24, c = oo - p*24;
    return 96*p + 72 + c;
}

// bf16 m16n8k16 MMA, fp32 accumulate
__device__ __forceinline__ void mma16816(float* c,
                                         unsigned a0, unsigned a1,
                                         unsigned a2, unsigned a3,
                                         unsigned b0, unsigned b1) {
    asm volatile(
        "mma.sync.aligned.m16n8k16.row.col.f32.bf16.bf16.f32 "
        "{%0,%1,%2,%3}, {%4,%5,%6,%7}, {%8,%9}, {%0,%1,%2,%3};"
        : "+f"(c[0]), "+f"(c[1]), "+f"(c[2]), "+f"(c[3])
        : "r"(a0), "r"(a1), "r"(a2), "r"(a3), "r"(b0), "r"(b1));
}

#define XS 104    // bf16 smem row stride (qkv tiles)
#define FS 72     // bf16 smem row stride (final tiles, K=64)

// =============== Kernel 0: bf16 conversions + coo transpose + inv =============
__global__ void __launch_bounds__(256) k_pre(const float* __restrict__ x,
                                             const float* __restrict__ W,
                                             const float* __restrict__ Wf,
                                             const int* __restrict__ coo0,
                                             const int* __restrict__ coo1,
                                             const int* __restrict__ a2a) {
    const int blk = blockIdx.x, tid = threadIdx.x;
    if (blk < 192) {
        const int base = blk*4096 + tid;
#pragma unroll
        for (int j = 0; j < 16; j++) {
            int idx = base + j*256;
            float2 v = *(const float2*)&x[idx*2];
            *(__nv_bfloat162*)&g_xh[idx*2] = __float22bfloat162_rn(v);
        }
    } else if (blk == 192) {
        for (int i = tid; i < 208*96; i += 256) {
            int o = i / 96, k = i - o*96;
            g_wh[i] = __float2bfloat16_rn(W[rowmap_all(o)*97 + k]);
        }
        for (int i = tid; i < 96*64; i += 256) {
            int o = i / 64, k = i - o*64;
            g_wf[i] = __float2bfloat16_rn(Wf[o*97 + 32 + k]);
        }
        if (tid < 208) g_bias[tid] = W[rowmap_all(tid)*97 + 96];
        g_inv[tid] = -1; g_inv[tid + 256] = -1;
        __syncthreads();
        if (tid < A2LEN) g_inv[a2a[tid]] = tid;
    } else {
        const int pb = blk - 193;               // 0..63
#pragma unroll
        for (int j = 0; j < 2; j++) {
            int g = pb*512 + j*256 + tid;
            int i = g >> 14;
            int e = g & 16383;
            const int* coo = i ? coo1 : coo0;
            int src = coo[e*3 + 1];
            int tok = e >> 5, r = e & 31;
            g_src[i*16384 + r*512 + tok] = src;
        }
    }
}

// =============== Kernel A: GEMMs (331 blocks, 256 thr) ========================
// blocks [0,256):   qkv bf16 MMA, tile 64 tok x 128 out
// blocks [256,331): dense-head qkv bf16 MMA, tile 64 rows x 72(+8) out
__global__ void __launch_bounds__(256, 4) k_gemms(const int* __restrict__ a2a) {
    extern __shared__ __align__(16) float sm[];
    const int blk = blockIdx.x;
    const int tid = threadIdx.x;

    if (blk < 256) {
        __nv_bfloat16* sX  = (__nv_bfloat16*)sm;     // [64][XS]
        __nv_bfloat16* sWh = sX + 64*XS;             // [128][XS]
        float*         sB  = (float*)(sWh + 128*XS); // [128]
        const int t0 = blk * 64;

        for (int idx = tid; idx < 768; idx += 256) {          // X: 64 x 12 uint4
            int row = idx / 12, q = idx - row*12;
            *(uint4*)&sX[row*XS + q*8] =
                *(const uint4*)&g_xh[(t0 + row)*96 + q*8];
        }
        for (int idx = tid; idx < 1536; idx += 256) {         // W: 128 x 12 uint4
            int row = idx / 12, q = idx - row*12;
            *(uint4*)&sWh[row*XS + q*8] =
                *(const uint4*)&g_wh[row*96 + q*8];
        }
        if (tid < 128) sB[tid] = g_bias[tid];
        __syncthreads();

        const int warp = tid >> 5, lane = tid & 31;
        const int mw = (warp & 3) * 16;
        const int nw = (warp >> 2) * 64;
        const int gr = lane >> 2;
        const int qp = (lane & 3) * 2;

        float acc[8][4];
#pragma unroll
        for (int n = 0; n < 8; n++)
#pragma unroll
            for (int j = 0; j < 4; j++) acc[n][j] = 0.f;

        const __nv_bfloat16* ab = &sX[(mw + gr)*XS + qp];
#pragma unroll
        for (int ks = 0; ks < 6; ks++) {
            const int k0 = ks * 16;
            unsigned a0 = *(const unsigned*)(ab + k0);
            unsigned a1 = *(const unsigned*)(ab + k0 + 8*XS);
            unsigned a2 = *(const unsigned*)(ab + k0 + 8);
            unsigned a3 = *(const unsigned*)(ab + k0 + 8*XS + 8);
#pragma unroll
            for (int n = 0; n < 8; n++) {
                const __nv_bfloat16* bb = &sWh[(nw + n*8 + gr)*XS + k0 + qp];
                unsigned b0 = *(const unsigned*)bb;
                unsigned b1 = *(const unsigned*)(bb + 8);
                mma16816(acc[n], a0, a1, a2, a3, b0, b1);
            }
        }
        const int r0 = t0 + mw + gr;
#pragma unroll
        for (int n = 0; n < 8; n++) {
            int col = nw + n*8 + qp;
            float bb0 = sB[col], bb1 = sB[col + 1];
            *(float2*)&g_y[r0*YW + col] =
                make_float2(acc[n][0] + bb0, acc[n][1] + bb1);
            *(float2*)&g_y[(r0 + 8)*YW + col] =
                make_float2(acc[n][2] + bb0, acc[n][3] + bb1);
        }
    } else {
        // dense-head qkv: 64 a2a-rows x 80 outputs (72 real)
        const int d = blk - 256;                     // 0..74
        __nv_bfloat16* sX  = (__nv_bfloat16*)sm;     // [64][XS]
        __nv_bfloat16* sWh = sX + 64*XS;             // [80][XS]
        float*         sB  = (float*)(sWh + 80*XS);  // [80]
        int*           sRow = (int*)(sB + 80);       // [64]
        const int r0 = d * 64;

        if (tid < 64) {
            int r = r0 + tid;
            int b = r / A2LEN, dd = r - b*A2LEN;
            sRow[tid] = b*NTOK + a2a[dd];
        }
        __syncthreads();
        for (int idx = tid; idx < 768; idx += 256) {
            int row = idx / 12, q = idx - row*12;
            *(uint4*)&sX[row*XS + q*8] =
                *(const uint4*)&g_xh[sRow[row]*96 + q*8];
        }
        for (int idx = tid; idx < 960; idx += 256) {
            int row = idx / 12, q = idx - row*12;
            *(uint4*)&sWh[row*XS + q*8] =
                *(const uint4*)&g_wh[(128 + row)*96 + q*8];
        }
        if (tid < 80) sB[tid] = g_bias[128 + tid];
        __syncthreads();

        const int warp = tid >> 5, lane = tid & 31;
        const int mw = (warp & 3) * 16;
        const int nw = (warp >> 2) * 40;
        const int gr = lane >> 2;
        const int qp = (lane & 3) * 2;

        float acc[5][4];
#pragma unroll
        for (int n = 0; n < 5; n++)
#pragma unroll
            for (int j = 0; j < 4; j++) acc[n][j] = 0.f;

        const __nv_bfloat16* ab = &sX[(mw + gr)*XS + qp];
#pragma unroll
        for (int ks = 0; ks < 6; ks++) {
            const int k0 = ks * 16;
            unsigned a0 = *(const unsigned*)(ab + k0);
            unsigned a1 = *(const unsigned*)(ab + k0 + 8*XS);
            unsigned a2 = *(const unsigned*)(ab + k0 + 8);
            unsigned a3 = *(const unsigned*)(ab + k0 + 8*XS + 8);
#pragma unroll
            for (int n = 0; n < 5; n++) {
                const __nv_bfloat16* bb = &sWh[(nw + n*8 + gr)*XS + k0 + qp];
                unsigned b0 = *(const unsigned*)bb;
                unsigned b1 = *(const unsigned*)(bb + 8);
                mma16816(acc[n], a0, a1, a2, a3, b0, b1);
            }
        }
        const int rr = r0 + mw + gr;
#pragma unroll
        for (int n = 0; n < 5; n++) {
            int col = nw + n*8 + qp;
            if (col < 72) {
                int p = col / 24, c = col - p*24;
                float bb0 = sB[col], bb1 = sB[col + 1];
                *(float2*)&g_yd[p*(NDR*24) + rr*24 + c] =
                    make_float2(acc[n][0] + bb0, acc[n][1] + bb1);
                *(float2*)&g_yd[p*(NDR*24) + (rr + 8)*24 + c] =
                    make_float2(acc[n][2] + bb0, acc[n][3] + bb1);
            }
        }
    }
}

// =============== Kernel B: both attentions (352 blocks, 256 thr) ==============
#define SPLH (NTOK*12)
__global__ void __launch_bounds__(256) k_attn() {
    extern __shared__ __align__(16) float smf[];
    const int blk = blockIdx.x;
    const int tid = threadIdx.x;

    if (blk < 256) {
        __half* hs = (__half*)smf;               // 48 KB
        const int b    = blk >> 3;
        const int i    = (blk >> 2) & 1;
        const int quar = blk & 3;

        for (int idx = tid; idx < 10240; idx += 256) {
            int p    = idx / 5120;
            int rem  = idx - p*5120;
            int hp   = rem / 2560;
            int rem2 = rem - hp*2560;
            int tok  = rem2 / 5;
            int c    = rem2 - tok*5;
            float2 v = *(const float2*)&g_y[(b*NTOK + tok)*YW + 40 + p*40 + i*20 + hp*10 + 2*c];
            *(__half2*)&hs[(p*2 + hp)*SPLH + tok*12 + 2*c] = __float22half2_rn(v);
        }
        __syncthreads();

        const int t  = quar*128 + (tid >> 1);
        const int hp = tid & 1;
        const __half* sK = hs + hp*SPLH;
        const __half* sV = hs + (2 + hp)*SPLH;
        const float* qp = &g_y[(b*NTOK + t)*YW + i*20 + hp*10];
        __half2 qh[5];
#pragma unroll
        for (int w = 0; w < 5; w++)
            qh[w] = __floats2half2_rn(qp[2*w], qp[2*w+1]);
        const int* srcp = &g_src[i*16384 + t];
        const float scale = 0.44721359549995793f;   // 1/sqrt(5)
        float l0 = 0.f, l1 = 0.f;
        __half2 acc0 = __float2half2_rn(0.f), acc1 = acc0, acc2 = acc0,
                acc3 = acc0, acc4 = acc0;
#pragma unroll 4
        for (int r = 0; r < 32; r++) {
            int base = srcp[r*512] * 12;
            uint2 ka = *(const uint2*)&sK[base];
            uint2 kb = *(const uint2*)&sK[base + 4];
            unsigned int kc = *(const unsigned int*)&sK[base + 8];
            __half2 d0 = __habs2(__hsub2(qh[0], *(const __half2*)&ka.x));
            __half2 d1 = __habs2(__hsub2(qh[1], *(const __half2*)&ka.y));
            __half2 d2 = __habs2(__hsub2(qh[2], *(const __half2*)&kb.x));
            __half2 d3 = __habs2(__hsub2(qh[3], *(const __half2*)&kb.y));
            __half2 d4 = __habs2(__hsub2(qh[4], *(const __half2*)&kc));
            __half2 u = __hadd2(d0, d1);
            __half2 v = __hadd2(d3, d4);
            __half2 uv = __hadd2(__halves2half2(__low2half(u),  __low2half(v)),
                                 __halves2half2(__high2half(u), __high2half(v)));
            __half2 s2 = __hadd2(uv, d2);
            float2 sf = __half22float2(s2);
            float p0 = __expf(-sf.x * scale);
            float p1 = __expf(-sf.y * scale);
            l0 += p0; l1 += p1;
            __half h0 = __float2half_rn(p0), h1 = __float2half_rn(p1);
            __half2 pp00 = __halves2half2(h0, h0);
            __half2 pp01 = __halves2half2(h0, h1);
            __half2 pp11 = __halves2half2(h1, h1);
            uint2 va = *(const uint2*)&sV[base];
            uint2 vb = *(const uint2*)&sV[base + 4];
            unsigned int vc = *(const unsigned int*)&sV[base + 8];
            acc0 = __hfma2(pp00, *(const __half2*)&va.x, acc0);
            acc1 = __hfma2(pp00, *(const __half2*)&va.y, acc1);
            acc2 = __hfma2(pp01, *(const __half2*)&vb.x, acc2);
            acc3 = __hfma2(pp11, *(const __half2*)&vb.y, acc3);
            acc4 = __hfma2(pp11, *(const __half2*)&vc,   acc4);
        }
        float inv0 = 1.0f / l0, inv1 = 1.0f / l1;
        float2 f0 = __half22float2(acc0);
        float2 f1 = __half22float2(acc1);
        float2 f2 = __half22float2(acc2);
        float2 f3 = __half22float2(acc3);
        float2 f4 = __half22float2(acc4);
        float* op = &g_sp[(b*NTOK + t)*40 + i*20 + hp*10];
        *(float2*)&op[0] = make_float2(f0.x*inv0, f0.y*inv0);
        *(float2*)&op[2] = make_float2(f1.x*inv0, f1.y*inv0);
        *(float2*)&op[4] = make_float2(f2.x*inv0, f2.y*inv1);
        *(float2*)&op[6] = make_float2(f3.x*inv1, f3.y*inv1);
        *(float2*)&op[8] = make_float2(f4.x*inv1, f4.y*inv1);
    } else {
        const int idx = blk - 256;
        const int b     = idx & 31;
        const int d0    = (idx >> 5) * 64;
        float* sK = smf;
        float* sV = smf + A2LEN*24;
        const int P = NDR * 24;
        for (int j = tid; j < A2LEN*24; j += 256) {
            sK[j] = g_yd[P   + b*A2LEN*24 + j];
            sV[j] = g_yd[2*P + b*A2LEN*24 + j];
        }
        __syncthreads();
        const int dl = tid >> 2, h = tid & 3;
        const int d = d0 + dl;
        if (d >= A2LEN) return;
        const float* qp = &g_yd[(b*A2LEN + d)*24 + h*6];
        float q[6];
#pragma unroll
        for (int w = 0; w < 6; w++) q[w] = qp[w];
        const float scale = 0.4082482904638631f;    // 1/sqrt(6)
        float l = 0.f;
        float acc[6] = {0.f,0.f,0.f,0.f,0.f,0.f};
#pragma unroll 2
        for (int s = 0; s < A2LEN; s++) {
            const float* kp = &sK[s*24 + h*6];
            float2 ka = *(const float2*)kp;
            float2 kb = *(const float2*)(kp + 2);
            float2 kc = *(const float2*)(kp + 4);
            float ds = fabsf(q[0]-ka.x) + fabsf(q[1]-ka.y) + fabsf(q[2]-kb.x)
                     + fabsf(q[3]-kb.y) + fabsf(q[4]-kc.x) + fabsf(q[5]-kc.y);
            float p = __expf(-ds * scale);
            l += p;
            const float* vp = &sV[s*24 + h*6];
            float2 va = *(const float2*)vp;
            float2 vb = *(const float2*)(vp + 2);
            float2 vc = *(const float2*)(vp + 4);
            acc[0] += p*va.x; acc[1] += p*va.y; acc[2] += p*vb.x;
            acc[3] += p*vb.y; acc[4] += p*vc.x; acc[5] += p*vc.y;
        }
        {
            float ds = fabsf(q[0]) + fabsf(q[1]) + fabsf(q[2])
                     + fabsf(q[3]) + fabsf(q[4]) + fabsf(q[5]);
            l += __expf(-ds * scale);
        }
        float inv = 1.0f / l;
        float* op = &g_dn[(b*A2LEN + d)*24 + h*6];
#pragma unroll
        for (int w = 0; w < 6; w++) op[w] = acc[w]*inv;
    }
}

// =============== Kernel C: out = x + SiLU(b) @ Wf^T + bias (bf16 MMA) =========
__global__ void __launch_bounds__(256) k_final(const float* __restrict__ x,
                                               const float* __restrict__ Wf,
                                               float* __restrict__ out) {
    __shared__ __align__(16) __nv_bfloat16 sY [64*FS];   // [tok][64 silu ch]
    __shared__ __align__(16) __nv_bfloat16 sWf[96*FS];   // [out][64 k]
    __shared__ __align__(16) float sB[96];
    const int t0 = blockIdx.x * 64;
    const int tid = threadIdx.x;

    for (int idx = tid; idx < 768; idx += 256) {          // Wf: 96 x 8 uint4
        int o = idx / 8, q = idx - o*8;
        *(uint4*)&sWf[o*FS + q*8] = *(const uint4*)&g_wf[o*64 + q*8];
    }
    if (tid < 96) sB[tid] = Wf[tid*97 + 96];
    for (int idx = tid; idx < 64*64; idx += 256) {
        int c = idx >> 6, t = idx & 63;
        int tt = t0 + t;
        float v;
        if (c < 40) {
            v = g_sp[tt*40 + c];
        } else {
            int b = tt >> 9, tok = tt & 511;
            int d = g_inv[tok];
            v = (d >= 0) ? g_dn[(b*A2LEN + d)*24 + (c - 40)] : 0.f;
        }
        float sg = 1.0f / (1.0f + __expf(-1.702f * v));
        sY[t*FS + c] = __float2bfloat16_rn(v * sg);
    }
    __syncthreads();

    const int warp = tid >> 5, lane = tid & 31;
    const int mw = (warp & 3) * 16;
    const int nw = (warp >> 2) * 48;
    const int gr = lane >> 2;
    const int qp = (lane & 3) * 2;

    float acc[6][4];
#pragma unroll
    for (int n = 0; n < 6; n++)
#pragma unroll
        for (int j = 0; j < 4; j++) acc[n][j] = 0.f;

    const __nv_bfloat16* ab = &sY[(mw + gr)*FS + qp];
#pragma unroll
    for (int ks = 0; ks < 4; ks++) {
        const int k0 = ks * 16;
        unsigned a0 = *(const unsigned*)(ab + k0);
        unsigned a1 = *(const unsigned*)(ab + k0 + 8*FS);
        unsigned a2 = *(const unsigned*)(ab + k0 + 8);
        unsigned a3 = *(const unsigned*)(ab + k0 + 8*FS + 8);
#pragma unroll
        for (int n = 0; n < 6; n++) {
            const __nv_bfloat16* bb = &sWf[(nw + n*8 + gr)*FS + k0 + qp];
            unsigned b0 = *(const unsigned*)bb;
            unsigned b1 = *(const unsigned*)(bb + 8);
            mma16816(acc[n], a0, a1, a2, a3, b0, b1);
        }
    }
    const int r0 = t0 + mw + gr;
#pragma unroll
    for (int n = 0; n < 6; n++) {
        int col = nw + n*8 + qp;
        float bb0 = sB[col], bb1 = sB[col + 1];
        float2 x0 = *(const float2*)&x[r0*96 + col];
        float2 x1 = *(const float2*)&x[(r0 + 8)*96 + col];
        *(float2*)&out[r0*96 + col] =
            make_float2(acc[n][0] + bb0 + x0.x, acc[n][1] + bb1 + x0.y);
        *(float2*)&out[(r0 + 8)*96 + col] =
            make_float2(acc[n][2] + bb0 + x1.x, acc[n][3] + bb1 + x1.y);
    }
}

// ---------------- launch -------------------------------------------------------
extern "C" void kernel_launch(void* const* d_in, const int* in_sizes, int n_in,
                              void* d_out, int out_size) {
    const float* x    = (const float*)d_in[0];
    const float* wqv  = (const float*)d_in[1];
    const float* wf   = (const float*)d_in[2];
    const int*   coo0 = (const int*)d_in[3];
    const int*   coo1 = (const int*)d_in[4];
    const int*   a2a  = (const int*)d_in[5];
    float*       out  = (float*)d_out;
    (void)in_sizes; (void)n_in; (void)out_size;

    const int smemA = (64*XS + 128*XS) * 2 + 128 * 4;        // 40448
    const int smemB = 4 * SPLH * sizeof(__half);             // 49152
    static int inited = 0;
    if (!inited) {
        cudaFuncSetAttribute(k_gemms, cudaFuncAttributeMaxDynamicSharedMemorySize, smemA);
        cudaFuncSetAttribute(k_attn,  cudaFuncAttributeMaxDynamicSharedMemorySize, smemB);
        inited = 1;
    }

    k_pre  <<<257, 256>>>(x, wqv, wf, coo0, coo1, a2a);
    k_gemms<<<331, 256, smemA>>>(a2a);
    k_attn <<<352, 256, smemB>>>();
    k_final<<<256, 256>>>(x, wf, out);
}

// round 12
// speedup vs baseline: 1.1694x; 1.0325x over previous
#include <cuda_runtime.h>
#include <cuda_fp16.h>
#include <cuda_bf16.h>

#define BS    32
#define NTOK  512
#define A2LEN 150
#define NTOT  (BS*NTOK)          // 16384
#define NDR   (BS*A2LEN)         // 4800 = 75*64
#define YW    128                // compact y width (120 used + 8 pad)

// ---------------- scratch ----------------------------------------------------
__device__ float g_y  [NTOT * YW];
__device__ float g_yd [3 * NDR * 24];
__device__ __nv_bfloat16 g_yb[NTOT * 64]; // SiLU(b) channels 32..96, bf16
__device__ int   g_src[2 * NTOK * 32];    // [i][r][t]
__device__ __nv_bfloat16 g_xh[NTOT * 96]; // bf16 x
__device__ __nv_bfloat16 g_wh[208 * 96];  // bf16 Wqv rows: [0,128) compact, [128,208) dense
__device__ __nv_bfloat16 g_wf[96 * 64];   // bf16 fanout W (cols 32..96)
__device__ float g_bias[208];

__device__ __forceinline__ int rowmap(int o) {
    if (o < 40)  return 32 + o;
    if (o < 80)  return 88 + o;
    if (o < 120) return 144 + o;
    return 32;
}
__device__ __forceinline__ int rowmap_all(int o) {   // 0..207 -> Wqv row
    if (o < 128) return rowmap(o);
    int oo = o - 128; if (oo > 71) oo = 71;
    int p = oo / 24, c = oo - p*24;
    return 96*p + 72 + c;
}

// bf16 m16n8k16 MMA, fp32 accumulate
__device__ __forceinline__ void mma16816(float* c,
                                         unsigned a0, unsigned a1,
                                         unsigned a2, unsigned a3,
                                         unsigned b0, unsigned b1) {
    asm volatile(
        "mma.sync.aligned.m16n8k16.row.col.f32.bf16.bf16.f32 "
        "{%0,%1,%2,%3}, {%4,%5,%6,%7}, {%8,%9}, {%0,%1,%2,%3};"
        : "+f"(c[0]), "+f"(c[1]), "+f"(c[2]), "+f"(c[3])
        : "r"(a0), "r"(a1), "r"(a2), "r"(a3), "r"(b0), "r"(b1));
}

__device__ __forceinline__ float silu(float v) {
    return v / (1.0f + __expf(-1.702f * v));
}

#define XS 104    // bf16 smem row stride (qkv tiles)
#define FS 72     // bf16 smem row stride (final tiles, K=64)

// =============== Kernel 0: conversions + zero yb + coo transpose ==============
// grid 321: [0,192) x conv; 192: W conv + bias; [193,257) coo; [257,321) zero yb
__global__ void __launch_bounds__(256) k_pre(const float* __restrict__ x,
                                             const float* __restrict__ W,
                                             const float* __restrict__ Wf,
                                             const int* __restrict__ coo0,
                                             const int* __restrict__ coo1) {
    const int blk = blockIdx.x, tid = threadIdx.x;
    if (blk < 192) {
        const int base = blk*4096 + tid;
#pragma unroll
        for (int j = 0; j < 16; j++) {
            int idx = base + j*256;
            float2 v = *(const float2*)&x[idx*2];
            *(__nv_bfloat162*)&g_xh[idx*2] = __float22bfloat162_rn(v);
        }
    } else if (blk == 192) {
        for (int i = tid; i < 208*96; i += 256) {
            int o = i / 96, k = i - o*96;
            g_wh[i] = __float2bfloat16_rn(W[rowmap_all(o)*97 + k]);
        }
        for (int i = tid; i < 96*64; i += 256) {
            int o = i / 64, k = i - o*64;
            g_wf[i] = __float2bfloat16_rn(Wf[o*97 + 32 + k]);
        }
        if (tid < 208) g_bias[tid] = W[rowmap_all(tid)*97 + 96];
    } else if (blk < 257) {
        const int pb = blk - 193;               // 0..63
#pragma unroll
        for (int j = 0; j < 2; j++) {
            int g = pb*512 + j*256 + tid;
            int i = g >> 14;
            int e = g & 16383;
            const int* coo = i ? coo1 : coo0;
            int src = coo[e*3 + 1];
            int tok = e >> 5, r = e & 31;
            g_src[i*16384 + r*512 + tok] = src;
        }
    } else {
        const int zb = blk - 257;               // 0..63, zero g_yb (2MB)
        uint4 z = make_uint4(0,0,0,0);
#pragma unroll
        for (int j = 0; j < 8; j++)
            *(uint4*)&g_yb[(zb*2048 + j*256 + tid)*8] = z;
    }
}

// =============== Kernel A: GEMMs (331 blocks, 256 thr) ========================
__global__ void __launch_bounds__(256, 4) k_gemms(const int* __restrict__ a2a) {
    extern __shared__ __align__(16) float sm[];
    const int blk = blockIdx.x;
    const int tid = threadIdx.x;

    if (blk < 256) {
        __nv_bfloat16* sX  = (__nv_bfloat16*)sm;     // [64][XS]
        __nv_bfloat16* sWh = sX + 64*XS;             // [128][XS]
        float*         sB  = (float*)(sWh + 128*XS); // [128]
        const int t0 = blk * 64;

        for (int idx = tid; idx < 768; idx += 256) {
            int row = idx / 12, q = idx - row*12;
            *(uint4*)&sX[row*XS + q*8] =
                *(const uint4*)&g_xh[(t0 + row)*96 + q*8];
        }
        for (int idx = tid; idx < 1536; idx += 256) {
            int row = idx / 12, q = idx - row*12;
            *(uint4*)&sWh[row*XS + q*8] =
                *(const uint4*)&g_wh[row*96 + q*8];
        }
        if (tid < 128) sB[tid] = g_bias[tid];
        __syncthreads();

        const int warp = tid >> 5, lane = tid & 31;
        const int mw = (warp & 3) * 16;
        const int nw = (warp >> 2) * 64;
        const int gr = lane >> 2;
        const int qp = (lane & 3) * 2;

        float acc[8][4];
#pragma unroll
        for (int n = 0; n < 8; n++)
#pragma unroll
            for (int j = 0; j < 4; j++) acc[n][j] = 0.f;

        const __nv_bfloat16* ab = &sX[(mw + gr)*XS + qp];
#pragma unroll
        for (int ks = 0; ks < 6; ks++) {
            const int k0 = ks * 16;
            unsigned a0 = *(const unsigned*)(ab + k0);
            unsigned a1 = *(const unsigned*)(ab + k0 + 8*XS);
            unsigned a2 = *(const unsigned*)(ab + k0 + 8);
            unsigned a3 = *(const unsigned*)(ab + k0 + 8*XS + 8);
#pragma unroll
            for (int n = 0; n < 8; n++) {
                const __nv_bfloat16* bb = &sWh[(nw + n*8 + gr)*XS + k0 + qp];
                unsigned b0 = *(const unsigned*)bb;
                unsigned b1 = *(const unsigned*)(bb + 8);
                mma16816(acc[n], a0, a1, a2, a3, b0, b1);
            }
        }
        const int r0 = t0 + mw + gr;
#pragma unroll
        for (int n = 0; n < 8; n++) {
            int col = nw + n*8 + qp;
            float bb0 = sB[col], bb1 = sB[col + 1];
            *(float2*)&g_y[r0*YW + col] =
                make_float2(acc[n][0] + bb0, acc[n][1] + bb1);
            *(float2*)&g_y[(r0 + 8)*YW + col] =
                make_float2(acc[n][2] + bb0, acc[n][3] + bb1);
        }
    } else {
        const int d = blk - 256;                     // 0..74
        __nv_bfloat16* sX  = (__nv_bfloat16*)sm;     // [64][XS]
        __nv_bfloat16* sWh = sX + 64*XS;             // [80][XS]
        float*         sB  = (float*)(sWh + 80*XS);  // [80]
        int*           sRow = (int*)(sB + 80);       // [64]
        const int r0 = d * 64;

        if (tid < 64) {
            int r = r0 + tid;
            int b = r / A2LEN, dd = r - b*A2LEN;
            sRow[tid] = b*NTOK + a2a[dd];
        }
        __syncthreads();
        for (int idx = tid; idx < 768; idx += 256) {
            int row = idx / 12, q = idx - row*12;
            *(uint4*)&sX[row*XS + q*8] =
                *(const uint4*)&g_xh[sRow[row]*96 + q*8];
        }
        for (int idx = tid; idx < 960; idx += 256) {
            int row = idx / 12, q = idx - row*12;
            *(uint4*)&sWh[row*XS + q*8] =
                *(const uint4*)&g_wh[(128 + row)*96 + q*8];
        }
        if (tid < 80) sB[tid] = g_bias[128 + tid];
        __syncthreads();

        const int warp = tid >> 5, lane = tid & 31;
        const int mw = (warp & 3) * 16;
        const int nw = (warp >> 2) * 40;
        const int gr = lane >> 2;
        const int qp = (lane & 3) * 2;

        float acc[5][4];
#pragma unroll
        for (int n = 0; n < 5; n++)
#pragma unroll
            for (int j = 0; j < 4; j++) acc[n][j] = 0.f;

        const __nv_bfloat16* ab = &sX[(mw + gr)*XS + qp];
#pragma unroll
        for (int ks = 0; ks < 6; ks++) {
            const int k0 = ks * 16;
            unsigned a0 = *(const unsigned*)(ab + k0);
            unsigned a1 = *(const unsigned*)(ab + k0 + 8*XS);
            unsigned a2 = *(const unsigned*)(ab + k0 + 8);
            unsigned a3 = *(const unsigned*)(ab + k0 + 8*XS + 8);
#pragma unroll
            for (int n = 0; n < 5; n++) {
                const __nv_bfloat16* bb = &sWh[(nw + n*8 + gr)*XS + k0 + qp];
                unsigned b0 = *(const unsigned*)bb;
                unsigned b1 = *(const unsigned*)(bb + 8);
                mma16816(acc[n], a0, a1, a2, a3, b0, b1);
            }
        }
        const int rr = r0 + mw + gr;
#pragma unroll
        for (int n = 0; n < 5; n++) {
            int col = nw + n*8 + qp;
            if (col < 72) {
                int p = col / 24, c = col - p*24;
                float bb0 = sB[col], bb1 = sB[col + 1];
                *(float2*)&g_yd[p*(NDR*24) + rr*24 + c] =
                    make_float2(acc[n][0] + bb0, acc[n][1] + bb1);
                *(float2*)&g_yd[p*(NDR*24) + (rr + 8)*24 + c] =
                    make_float2(acc[n][2] + bb0, acc[n][3] + bb1);
            }
        }
    }
}

// =============== Kernel B: attentions + SiLU -> g_yb (352 blocks) =============
#define SPLH (NTOK*12)
__global__ void __launch_bounds__(256) k_attn(const int* __restrict__ a2a) {
    extern __shared__ __align__(16) float smf[];
    const int blk = blockIdx.x;
    const int tid = threadIdx.x;

    if (blk < 256) {
        __half* hs = (__half*)smf;               // 48 KB
        const int b    = blk >> 3;
        const int i    = (blk >> 2) & 1;
        const int quar = blk & 3;

        for (int idx = tid; idx < 10240; idx += 256) {
            int p    = idx / 5120;
            int rem  = idx - p*5120;
            int hp   = rem / 2560;
            int rem2 = rem - hp*2560;
            int tok  = rem2 / 5;
            int c    = rem2 - tok*5;
            float2 v = *(const float2*)&g_y[(b*NTOK + tok)*YW + 40 + p*40 + i*20 + hp*10 + 2*c];
            *(__half2*)&hs[(p*2 + hp)*SPLH + tok*12 + 2*c] = __float22half2_rn(v);
        }
        __syncthreads();

        const int t  = quar*128 + (tid >> 1);
        const int hp = tid & 1;
        const __half* sK = hs + hp*SPLH;
        const __half* sV = hs + (2 + hp)*SPLH;
        const float* qp = &g_y[(b*NTOK + t)*YW + i*20 + hp*10];
        __half2 qh[5];
#pragma unroll
        for (int w = 0; w < 5; w++)
            qh[w] = __floats2half2_rn(qp[2*w], qp[2*w+1]);
        const int* srcp = &g_src[i*16384 + t];
        const float scale = 0.44721359549995793f;   // 1/sqrt(5)
        float l0 = 0.f, l1 = 0.f;
        __half2 acc0 = __float2half2_rn(0.f), acc1 = acc0, acc2 = acc0,
                acc3 = acc0, acc4 = acc0;
#pragma unroll 4
        for (int r = 0; r < 32; r++) {
            int base = srcp[r*512] * 12;
            uint2 ka = *(const uint2*)&sK[base];
            uint2 kb = *(const uint2*)&sK[base + 4];
            unsigned int kc = *(const unsigned int*)&sK[base + 8];
            __half2 d0 = __habs2(__hsub2(qh[0], *(const __half2*)&ka.x));
            __half2 d1 = __habs2(__hsub2(qh[1], *(const __half2*)&ka.y));
            __half2 d2 = __habs2(__hsub2(qh[2], *(const __half2*)&kb.x));
            __half2 d3 = __habs2(__hsub2(qh[3], *(const __half2*)&kb.y));
            __half2 d4 = __habs2(__hsub2(qh[4], *(const __half2*)&kc));
            __half2 u = __hadd2(d0, d1);
            __half2 v = __hadd2(d3, d4);
            __half2 uv = __hadd2(__halves2half2(__low2half(u),  __low2half(v)),
                                 __halves2half2(__high2half(u), __high2half(v)));
            __half2 s2 = __hadd2(uv, d2);
            float2 sf = __half22float2(s2);
            float p0 = __expf(-sf.x * scale);
            float p1 = __expf(-sf.y * scale);
            l0 += p0; l1 += p1;
            __half h0 = __float2half_rn(p0), h1 = __float2half_rn(p1);
            __half2 pp00 = __halves2half2(h0, h0);
            __half2 pp01 = __halves2half2(h0, h1);
            __half2 pp11 = __halves2half2(h1, h1);
            uint2 va = *(const uint2*)&sV[base];
            uint2 vb = *(const uint2*)&sV[base + 4];
            unsigned int vc = *(const unsigned int*)&sV[base + 8];
            acc0 = __hfma2(pp00, *(const __half2*)&va.x, acc0);
            acc1 = __hfma2(pp00, *(const __half2*)&va.y, acc1);
            acc2 = __hfma2(pp01, *(const __half2*)&vb.x, acc2);
            acc3 = __hfma2(pp11, *(const __half2*)&vb.y, acc3);
            acc4 = __hfma2(pp11, *(const __half2*)&vc,   acc4);
        }
        float inv0 = 1.0f / l0, inv1 = 1.0f / l1;
        float2 f0 = __half22float2(acc0);
        float2 f1 = __half22float2(acc1);
        float2 f2 = __half22float2(acc2);
        float2 f3 = __half22float2(acc3);
        float2 f4 = __half22float2(acc4);
        float o_[10] = { f0.x*inv0, f0.y*inv0, f1.x*inv0, f1.y*inv0,
                         f2.x*inv0, f2.y*inv1, f3.x*inv1, f3.y*inv1,
                         f4.x*inv1, f4.y*inv1 };
        __nv_bfloat16* op = &g_yb[(b*NTOK + t)*64 + i*20 + hp*10];
#pragma unroll
        for (int w = 0; w < 5; w++)
            *(__nv_bfloat162*)&op[2*w] =
                __float22bfloat162_rn(make_float2(silu(o_[2*w]), silu(o_[2*w+1])));
    } else {
        const int idx = blk - 256;
        const int b     = idx & 31;
        const int d0    = (idx >> 5) * 64;
        float* sK = smf;
        float* sV = smf + A2LEN*24;
        const int P = NDR * 24;
        for (int j = tid; j < A2LEN*24; j += 256) {
            sK[j] = g_yd[P   + b*A2LEN*24 + j];
            sV[j] = g_yd[2*P + b*A2LEN*24 + j];
        }
        __syncthreads();
        const int dl = tid >> 2, h = tid & 3;
        const int d = d0 + dl;
        if (d >= A2LEN) return;
        const float* qp = &g_yd[(b*A2LEN + d)*24 + h*6];
        float q[6];
#pragma unroll
        for (int w = 0; w < 6; w++) q[w] = qp[w];
        const float scale = 0.4082482904638631f;    // 1/sqrt(6)
        float l = 0.f;
        float acc[6] = {0.f,0.f,0.f,0.f,0.f,0.f};
#pragma unroll 2
        for (int s = 0; s < A2LEN; s++) {
            const float* kp = &sK[s*24 + h*6];
            float2 ka = *(const float2*)kp;
            float2 kb = *(const float2*)(kp + 2);
            float2 kc = *(const float2*)(kp + 4);
            float ds = fabsf(q[0]-ka.x) + fabsf(q[1]-ka.y) + fabsf(q[2]-kb.x)
                     + fabsf(q[3]-kb.y) + fabsf(q[4]-kc.x) + fabsf(q[5]-kc.y);
            float p = __expf(-ds * scale);
            l += p;
            const float* vp = &sV[s*24 + h*6];
            float2 va = *(const float2*)vp;
            float2 vb = *(const float2*)(vp + 2);
            float2 vc = *(const float2*)(vp + 4);
            acc[0] += p*va.x; acc[1] += p*va.y; acc[2] += p*vb.x;
            acc[3] += p*vb.y; acc[4] += p*vc.x; acc[5] += p*vc.y;
        }
        {
            float ds = fabsf(q[0]) + fabsf(q[1]) + fabsf(q[2])
                     + fabsf(q[3]) + fabsf(q[4]) + fabsf(q[5]);
            l += __expf(-ds * scale);
        }
        float inv = 1.0f / l;
        int row = b*NTOK + a2a[d];
        __nv_bfloat16* op = &g_yb[row*64 + 40 + h*6];
#pragma unroll
        for (int w = 0; w < 3; w++)
            *(__nv_bfloat162*)&op[2*w] =
                __float22bfloat162_rn(make_float2(silu(acc[2*w]*inv),
                                                  silu(acc[2*w+1]*inv)));
    }
}

// =============== Kernel C: out = x + yb @ Wf^T + bias (bf16 MMA, 512 blks) ====
__global__ void __launch_bounds__(256) k_final(const float* __restrict__ x,
                                               const float* __restrict__ Wf,
                                               float* __restrict__ out) {
    __shared__ __align__(16) __nv_bfloat16 sY [32*FS];
    __shared__ __align__(16) __nv_bfloat16 sWf[96*FS];
    __shared__ __align__(16) float sB[96];
    const int t0 = blockIdx.x * 32;
    const int tid = threadIdx.x;

    for (int idx = tid; idx < 256; idx += 256) {          // Y: 32 x 8 uint4
        int t = idx >> 3, q = idx & 7;
        *(uint4*)&sY[t*FS + q*8] = *(const uint4*)&g_yb[(t0 + t)*64 + q*8];
    }
    for (int idx = tid; idx < 768; idx += 256) {          // Wf: 96 x 8 uint4
        int o = idx / 8, q = idx - o*8;
        *(uint4*)&sWf[o*FS + q*8] = *(const uint4*)&g_wf[o*64 + q*8];
    }
    if (tid < 96) sB[tid] = Wf[tid*97 + 96];
    __syncthreads();

    const int warp = tid >> 5, lane = tid & 31;
    const int mw = (warp & 1) * 16;
    const int nw = (warp >> 1) * 24;
    const int gr = lane >> 2;
    const int qp = (lane & 3) * 2;

    float acc[3][4];
#pragma unroll
    for (int n = 0; n < 3; n++)
#pragma unroll
        for (int j = 0; j < 4; j++) acc[n][j] = 0.f;

    const __nv_bfloat16* ab = &sY[(mw + gr)*FS + qp];
#pragma unroll
    for (int ks = 0; ks < 4; ks++) {
        const int k0 = ks * 16;
        unsigned a0 = *(const unsigned*)(ab + k0);
        unsigned a1 = *(const unsigned*)(ab + k0 + 8*FS);
        unsigned a2 = *(const unsigned*)(ab + k0 + 8);
        unsigned a3 = *(const unsigned*)(ab + k0 + 8*FS + 8);
#pragma unroll
        for (int n = 0; n < 3; n++) {
            const __nv_bfloat16* bb = &sWf[(nw + n*8 + gr)*FS + k0 + qp];
            unsigned b0 = *(const unsigned*)bb;
            unsigned b1 = *(const unsigned*)(bb + 8);
            mma16816(acc[n], a0, a1, a2, a3, b0, b1);
        }
    }
    const int r0 = t0 + mw + gr;
#pragma unroll
    for (int n = 0; n < 3; n++) {
        int col = nw + n*8 + qp;
        float bb0 = sB[col], bb1 = sB[col + 1];
        float2 x0 = *(const float2*)&x[r0*96 + col];
        float2 x1 = *(const float2*)&x[(r0 + 8)*96 + col];
        *(float2*)&out[r0*96 + col] =
            make_float2(acc[n][0] + bb0 + x0.x, acc[n][1] + bb1 + x0.y);
        *(float2*)&out[(r0 + 8)*96 + col] =
            make_float2(acc[n][2] + bb0 + x1.x, acc[n][3] + bb1 + x1.y);
    }
}

// ---------------- launch -------------------------------------------------------
extern "C" void kernel_launch(void* const* d_in, const int* in_sizes, int n_in,
                              void* d_out, int out_size) {
    const float* x    = (const float*)d_in[0];
    const float* wqv  = (const float*)d_in[1];
    const float* wf   = (const float*)d_in[2];
    const int*   coo0 = (const int*)d_in[3];
    const int*   coo1 = (const int*)d_in[4];
    const int*   a2a  = (const int*)d_in[5];
    float*       out  = (float*)d_out;
    (void)in_sizes; (void)n_in; (void)out_size;

    const int smemA = (64*XS + 128*XS) * 2 + 128 * 4;        // 40448
    const int smemB = 4 * SPLH * sizeof(__half);             // 49152
    static int inited = 0;
    if (!inited) {
        cudaFuncSetAttribute(k_gemms, cudaFuncAttributeMaxDynamicSharedMemorySize, smemA);
        cudaFuncSetAttribute(k_attn,  cudaFuncAttributeMaxDynamicSharedMemorySize, smemB);
        inited = 1;
    }

    k_pre  <<<321, 256>>>(x, wqv, wf, coo0, coo1);
    k_gemms<<<331, 256, smemA>>>(a2a);
    k_attn <<<352, 256, smemB>>>(a2a);
    k_final<<<512, 256>>>(x, wf, out);
}

// round 13
// speedup vs baseline: 1.4569x; 1.2458x over previous
#include <cuda_runtime.h>
#include <cuda_fp16.h>
#include <cuda_bf16.h>

#define BS    32
#define NTOK  512
#define A2LEN 150
#define NTOT  (BS*NTOK)          // 16384
#define NDR   (BS*A2LEN)         // 4800 = 75*64
#define YW    128                // compact y width (120 used + 8 pad)

// ---------------- scratch ----------------------------------------------------
__device__ float g_y  [NTOT * YW];
__device__ float g_yd [3 * NDR * 24];
__device__ __nv_bfloat16 g_yb[NTOT * 64]; // SiLU(b) channels 32..96, bf16
__device__ int   g_src[2 * NTOK * 32];    // [i][r][t]
__device__ __nv_bfloat16 g_wh[208 * 96];  // bf16 Wqv rows: [0,128) compact, [128,208) dense
__device__ __nv_bfloat16 g_wf[96 * 64];   // bf16 fanout W (cols 32..96)
__device__ float g_bias[208];

__device__ __forceinline__ int rowmap(int o) {
    if (o < 40)  return 32 + o;
    if (o < 80)  return 88 + o;
    if (o < 120) return 144 + o;
    return 32;
}
__device__ __forceinline__ int rowmap_all(int o) {   // 0..207 -> Wqv row
    if (o < 128) return rowmap(o);
    int oo = o - 128; if (oo > 71) oo = 71;
    int p = oo / 24, c = oo - p*24;
    return 96*p + 72 + c;
}

// bf16 m16n8k16 MMA, fp32 accumulate
__device__ __forceinline__ void mma16816(float* c,
                                         unsigned a0, unsigned a1,
                                         unsigned a2, unsigned a3,
                                         unsigned b0, unsigned b1) {
    asm volatile(
        "mma.sync.aligned.m16n8k16.row.col.f32.bf16.bf16.f32 "
        "{%0,%1,%2,%3}, {%4,%5,%6,%7}, {%8,%9}, {%0,%1,%2,%3};"
        : "+f"(c[0]), "+f"(c[1]), "+f"(c[2]), "+f"(c[3])
        : "r"(a0), "r"(a1), "r"(a2), "r"(a3), "r"(b0), "r"(b1));
}

__device__ __forceinline__ float silu(float v) {
    return v / (1.0f + __expf(-1.702f * v));
}

#define XS 104    // bf16 smem row stride (qkv tiles)
#define FS 72     // bf16 smem row stride (final tiles, K=64)

// =============== Kernel 0: weight conversions only (14 blocks) ================
__global__ void __launch_bounds__(256) k_pre(const float* __restrict__ W,
                                             const float* __restrict__ Wf) {
    const int blk = blockIdx.x, tid = threadIdx.x;
    if (blk < 13) {                           // 16 W rows per block
        const int o0 = blk * 16;
#pragma unroll
        for (int j = 0; j < 6; j++) {
            int i = j*256 + tid;              // 0..1535
            int o = o0 + i / 96, k = i % 96;
            g_wh[o*96 + k] = __float2bfloat16_rn(W[rowmap_all(o)*97 + k]);
        }
    } else {
        for (int i = tid; i < 96*64; i += 256) {
            int o = i / 64, k = i - o*64;
            g_wf[i] = __float2bfloat16_rn(Wf[o*97 + 32 + k]);
        }
        if (tid < 208) g_bias[tid] = W[rowmap_all(tid)*97 + 96];
    }
}

// =============== Kernel A: GEMMs + prep (459 blocks, 256 thr) =================
// [0,256) qkv MMA (x converted inline) | [256,331) dense-head MMA
// [331,395) coo transpose | [395,459) zero g_yb
__global__ void __launch_bounds__(256, 4) k_gemms(const float* __restrict__ x,
                                                  const int* __restrict__ coo0,
                                                  const int* __restrict__ coo1,
                                                  const int* __restrict__ a2a) {
    extern __shared__ __align__(16) float sm[];
    const int blk = blockIdx.x;
    const int tid = threadIdx.x;

    if (blk < 256) {
        __nv_bfloat16* sX  = (__nv_bfloat16*)sm;     // [64][XS]
        __nv_bfloat16* sWh = sX + 64*XS;             // [128][XS]
        float*         sB  = (float*)(sWh + 128*XS); // [128]
        const int t0 = blk * 64;

        for (int idx = tid; idx < 64*48; idx += 256) {        // X: convert inline
            int row = idx / 48, c = idx - row*48;
            float2 v = *(const float2*)&x[(t0 + row)*96 + 2*c];
            *(__nv_bfloat162*)&sX[row*XS + 2*c] = __float22bfloat162_rn(v);
        }
        for (int idx = tid; idx < 1536; idx += 256) {         // W: 128 x 12 uint4
            int row = idx / 12, q = idx - row*12;
            *(uint4*)&sWh[row*XS + q*8] =
                *(const uint4*)&g_wh[row*96 + q*8];
        }
        if (tid < 128) sB[tid] = g_bias[tid];
        __syncthreads();

        const int warp = tid >> 5, lane = tid & 31;
        const int mw = (warp & 3) * 16;
        const int nw = (warp >> 2) * 64;
        const int gr = lane >> 2;
        const int qp = (lane & 3) * 2;

        float acc[8][4];
#pragma unroll
        for (int n = 0; n < 8; n++)
#pragma unroll
            for (int j = 0; j < 4; j++) acc[n][j] = 0.f;

        const __nv_bfloat16* ab = &sX[(mw + gr)*XS + qp];
#pragma unroll
        for (int ks = 0; ks < 6; ks++) {
            const int k0 = ks * 16;
            unsigned a0 = *(const unsigned*)(ab + k0);
            unsigned a1 = *(const unsigned*)(ab + k0 + 8*XS);
            unsigned a2 = *(const unsigned*)(ab + k0 + 8);
            unsigned a3 = *(const unsigned*)(ab + k0 + 8*XS + 8);
#pragma unroll
            for (int n = 0; n < 8; n++) {
                const __nv_bfloat16* bb = &sWh[(nw + n*8 + gr)*XS + k0 + qp];
                unsigned b0 = *(const unsigned*)bb;
                unsigned b1 = *(const unsigned*)(bb + 8);
                mma16816(acc[n], a0, a1, a2, a3, b0, b1);
            }
        }
        const int r0 = t0 + mw + gr;
#pragma unroll
        for (int n = 0; n < 8; n++) {
            int col = nw + n*8 + qp;
            float bb0 = sB[col], bb1 = sB[col + 1];
            *(float2*)&g_y[r0*YW + col] =
                make_float2(acc[n][0] + bb0, acc[n][1] + bb1);
            *(float2*)&g_y[(r0 + 8)*YW + col] =
                make_float2(acc[n][2] + bb0, acc[n][3] + bb1);
        }
    } else if (blk < 331) {
        const int d = blk - 256;                     // 0..74
        __nv_bfloat16* sX  = (__nv_bfloat16*)sm;     // [64][XS]
        __nv_bfloat16* sWh = sX + 64*XS;             // [80][XS]
        float*         sB  = (float*)(sWh + 80*XS);  // [80]
        int*           sRow = (int*)(sB + 80);       // [64]
        const int r0 = d * 64;

        if (tid < 64) {
            int r = r0 + tid;
            int b = r / A2LEN, dd = r - b*A2LEN;
            sRow[tid] = b*NTOK + a2a[dd];
        }
        __syncthreads();
        for (int idx = tid; idx < 64*48; idx += 256) {        // X: convert inline
            int row = idx / 48, c = idx - row*48;
            float2 v = *(const float2*)&x[sRow[row]*96 + 2*c];
            *(__nv_bfloat162*)&sX[row*XS + 2*c] = __float22bfloat162_rn(v);
        }
        for (int idx = tid; idx < 960; idx += 256) {
            int row = idx / 12, q = idx - row*12;
            *(uint4*)&sWh[row*XS + q*8] =
                *(const uint4*)&g_wh[(128 + row)*96 + q*8];
        }
        if (tid < 80) sB[tid] = g_bias[128 + tid];
        __syncthreads();

        const int warp = tid >> 5, lane = tid & 31;
        const int mw = (warp & 3) * 16;
        const int nw = (warp >> 2) * 40;
        const int gr = lane >> 2;
        const int qp = (lane & 3) * 2;

        float acc[5][4];
#pragma unroll
        for (int n = 0; n < 5; n++)
#pragma unroll
            for (int j = 0; j < 4; j++) acc[n][j] = 0.f;

        const __nv_bfloat16* ab = &sX[(mw + gr)*XS + qp];
#pragma unroll
        for (int ks = 0; ks < 6; ks++) {
            const int k0 = ks * 16;
            unsigned a0 = *(const unsigned*)(ab + k0);
            unsigned a1 = *(const unsigned*)(ab + k0 + 8*XS);
            unsigned a2 = *(const unsigned*)(ab + k0 + 8);
            unsigned a3 = *(const unsigned*)(ab + k0 + 8*XS + 8);
#pragma unroll
            for (int n = 0; n < 5; n++) {
                const __nv_bfloat16* bb = &sWh[(nw + n*8 + gr)*XS + k0 + qp];
                unsigned b0 = *(const unsigned*)bb;
                unsigned b1 = *(const unsigned*)(bb + 8);
                mma16816(acc[n], a0, a1, a2, a3, b0, b1);
            }
        }
        const int rr = r0 + mw + gr;
#pragma unroll
        for (int n = 0; n < 5; n++) {
            int col = nw + n*8 + qp;
            if (col < 72) {
                int p = col / 24, c = col - p*24;
                float bb0 = sB[col], bb1 = sB[col + 1];
                *(float2*)&g_yd[p*(NDR*24) + rr*24 + c] =
                    make_float2(acc[n][0] + bb0, acc[n][1] + bb1);
                *(float2*)&g_yd[p*(NDR*24) + (rr + 8)*24 + c] =
                    make_float2(acc[n][2] + bb0, acc[n][3] + bb1);
            }
        }
    } else if (blk < 395) {
        const int pb = blk - 331;                // 0..63 coo transpose
#pragma unroll
        for (int j = 0; j < 2; j++) {
            int g = pb*512 + j*256 + tid;
            int i = g >> 14;
            int e = g & 16383;
            const int* coo = i ? coo1 : coo0;
            int src = coo[e*3 + 1];
            int tok = e >> 5, r = e & 31;
            g_src[i*16384 + r*512 + tok] = src;
        }
    } else {
        const int zb = blk - 395;                // 0..63 zero g_yb
        uint4 z = make_uint4(0,0,0,0);
#pragma unroll
        for (int j = 0; j < 8; j++)
            *(uint4*)&g_yb[(zb*2048 + j*256 + tid)*8] = z;
    }
}

// =============== Kernel B: attentions + SiLU -> g_yb (352 blocks) =============
#define SPLH (NTOK*12)
__global__ void __launch_bounds__(256) k_attn(const int* __restrict__ a2a) {
    extern __shared__ __align__(16) float smf[];
    const int blk = blockIdx.x;
    const int tid = threadIdx.x;

    if (blk < 256) {
        __half* hs = (__half*)smf;               // 48 KB
        const int b    = blk >> 3;
        const int i    = (blk >> 2) & 1;
        const int quar = blk & 3;

        for (int idx = tid; idx < 10240; idx += 256) {
            int p    = idx / 5120;
            int rem  = idx - p*5120;
            int hp   = rem / 2560;
            int rem2 = rem - hp*2560;
            int tok  = rem2 / 5;
            int c    = rem2 - tok*5;
            float2 v = *(const float2*)&g_y[(b*NTOK + tok)*YW + 40 + p*40 + i*20 + hp*10 + 2*c];
            *(__half2*)&hs[(p*2 + hp)*SPLH + tok*12 + 2*c] = __float22half2_rn(v);
        }
        __syncthreads();

        const int t  = quar*128 + (tid >> 1);
        const int hp = tid & 1;
        const __half* sK = hs + hp*SPLH;
        const __half* sV = hs + (2 + hp)*SPLH;
        const float* qp = &g_y[(b*NTOK + t)*YW + i*20 + hp*10];
        __half2 qh[5];
#pragma unroll
        for (int w = 0; w < 5; w++)
            qh[w] = __floats2half2_rn(qp[2*w], qp[2*w+1]);
        const int* srcp = &g_src[i*16384 + t];
        const float scale = 0.44721359549995793f;   // 1/sqrt(5)
        float l0 = 0.f, l1 = 0.f;
        __half2 acc0 = __float2half2_rn(0.f), acc1 = acc0, acc2 = acc0,
                acc3 = acc0, acc4 = acc0;
#pragma unroll 4
        for (int r = 0; r < 32; r++) {
            int base = srcp[r*512] * 12;
            uint2 ka = *(const uint2*)&sK[base];
            uint2 kb = *(const uint2*)&sK[base + 4];
            unsigned int kc = *(const unsigned int*)&sK[base + 8];
            __half2 d0 = __habs2(__hsub2(qh[0], *(const __half2*)&ka.x));
            __half2 d1 = __habs2(__hsub2(qh[1], *(const __half2*)&ka.y));
            __half2 d2 = __habs2(__hsub2(qh[2], *(const __half2*)&kb.x));
            __half2 d3 = __habs2(__hsub2(qh[3], *(const __half2*)&kb.y));
            __half2 d4 = __habs2(__hsub2(qh[4], *(const __half2*)&kc));
            __half2 u = __hadd2(d0, d1);
            __half2 v = __hadd2(d3, d4);
            __half2 uv = __hadd2(__halves2half2(__low2half(u),  __low2half(v)),
                                 __halves2half2(__high2half(u), __high2half(v)));
            __half2 s2 = __hadd2(uv, d2);
            float2 sf = __half22float2(s2);
            float p0 = __expf(-sf.x * scale);
            float p1 = __expf(-sf.y * scale);
            l0 += p0; l1 += p1;
            __half h0 = __float2half_rn(p0), h1 = __float2half_rn(p1);
            __half2 pp00 = __halves2half2(h0, h0);
            __half2 pp01 = __halves2half2(h0, h1);
            __half2 pp11 = __halves2half2(h1, h1);
            uint2 va = *(const uint2*)&sV[base];
            uint2 vb = *(const uint2*)&sV[base + 4];
            unsigned int vc = *(const unsigned int*)&sV[base + 8];
            acc0 = __hfma2(pp00, *(const __half2*)&va.x, acc0);
            acc1 = __hfma2(pp00, *(const __half2*)&va.y, acc1);
            acc2 = __hfma2(pp01, *(const __half2*)&vb.x, acc2);
            acc3 = __hfma2(pp11, *(const __half2*)&vb.y, acc3);
            acc4 = __hfma2(pp11, *(const __half2*)&vc,   acc4);
        }
        float inv0 = 1.0f / l0, inv1 = 1.0f / l1;
        float2 f0 = __half22float2(acc0);
        float2 f1 = __half22float2(acc1);
        float2 f2 = __half22float2(acc2);
        float2 f3 = __half22float2(acc3);
        float2 f4 = __half22float2(acc4);
        float o_[10] = { f0.x*inv0, f0.y*inv0, f1.x*inv0, f1.y*inv0,
                         f2.x*inv0, f2.y*inv1, f3.x*inv1, f3.y*inv1,
                         f4.x*inv1, f4.y*inv1 };
        __nv_bfloat16* op = &g_yb[(b*NTOK + t)*64 + i*20 + hp*10];
#pragma unroll
        for (int w = 0; w < 5; w++)
            *(__nv_bfloat162*)&op[2*w] =
                __float22bfloat162_rn(make_float2(silu(o_[2*w]), silu(o_[2*w+1])));
    } else {
        const int idx = blk - 256;
        const int b     = idx & 31;
        const int d0    = (idx >> 5) * 64;
        float* sK = smf;
        float* sV = smf + A2LEN*24;
        const int P = NDR * 24;
        for (int j = tid; j < A2LEN*24; j += 256) {
            sK[j] = g_yd[P   + b*A2LEN*24 + j];
            sV[j] = g_yd[2*P + b*A2LEN*24 + j];
        }
        __syncthreads();
        const int dl = tid >> 2, h = tid & 3;
        const int d = d0 + dl;
        if (d >= A2LEN) return;
        const float* qp = &g_yd[(b*A2LEN + d)*24 + h*6];
        float q[6];
#pragma unroll
        for (int w = 0; w < 6; w++) q[w] = qp[w];
        const float scale = 0.4082482904638631f;    // 1/sqrt(6)
        float l = 0.f;
        float acc[6] = {0.f,0.f,0.f,0.f,0.f,0.f};
#pragma unroll 2
        for (int s = 0; s < A2LEN; s++) {
            const float* kp = &sK[s*24 + h*6];
            float2 ka = *(const float2*)kp;
            float2 kb = *(const float2*)(kp + 2);
            float2 kc = *(const float2*)(kp + 4);
            float ds = fabsf(q[0]-ka.x) + fabsf(q[1]-ka.y) + fabsf(q[2]-kb.x)
                     + fabsf(q[3]-kb.y) + fabsf(q[4]-kc.x) + fabsf(q[5]-kc.y);
            float p = __expf(-ds * scale);
            l += p;
            const float* vp = &sV[s*24 + h*6];
            float2 va = *(const float2*)vp;
            float2 vb = *(const float2*)(vp + 2);
            float2 vc = *(const float2*)(vp + 4);
            acc[0] += p*va.x; acc[1] += p*va.y; acc[2] += p*vb.x;
            acc[3] += p*vb.y; acc[4] += p*vc.x; acc[5] += p*vc.y;
        }
        {
            float ds = fabsf(q[0]) + fabsf(q[1]) + fabsf(q[2])
                     + fabsf(q[3]) + fabsf(q[4]) + fabsf(q[5]);
            l += __expf(-ds * scale);
        }
        float inv = 1.0f / l;
        int row = b*NTOK + a2a[d];
        __nv_bfloat16* op = &g_yb[row*64 + 40 + h*6];
#pragma unroll
        for (int w = 0; w < 3; w++)
            *(__nv_bfloat162*)&op[2*w] =
                __float22bfloat162_rn(make_float2(silu(acc[2*w]*inv),
                                                  silu(acc[2*w+1]*inv)));
    }
}

// =============== Kernel C: out = x + yb @ Wf^T + bias (bf16 MMA, 512 blks) ====
__global__ void __launch_bounds__(256) k_final(const float* __restrict__ x,
                                               const float* __restrict__ Wf,
                                               float* __restrict__ out) {
    __shared__ __align__(16) __nv_bfloat16 sY [32*FS];
    __shared__ __align__(16) __nv_bfloat16 sWf[96*FS];
    __shared__ __align__(16) float sB[96];
    const int t0 = blockIdx.x * 32;
    const int tid = threadIdx.x;

    {
        int t = tid >> 3, q = tid & 7;
        *(uint4*)&sY[t*FS + q*8] = *(const uint4*)&g_yb[(t0 + t)*64 + q*8];
    }
    for (int idx = tid; idx < 768; idx += 256) {
        int o = idx / 8, q = idx - o*8;
        *(uint4*)&sWf[o*FS + q*8] = *(const uint4*)&g_wf[o*64 + q*8];
    }
    if (tid < 96) sB[tid] = Wf[tid*97 + 96];
    __syncthreads();

    const int warp = tid >> 5, lane = tid & 31;
    const int mw = (warp & 1) * 16;
    const int nw = (warp >> 1) * 24;
    const int gr = lane >> 2;
    const int qp = (lane & 3) * 2;

    float acc[3][4];
#pragma unroll
    for (int n = 0; n < 3; n++)
#pragma unroll
        for (int j = 0; j < 4; j++) acc[n][j] = 0.f;

    const __nv_bfloat16* ab = &sY[(mw + gr)*FS + qp];
#pragma unroll
    for (int ks = 0; ks < 4; ks++) {
        const int k0 = ks * 16;
        unsigned a0 = *(const unsigned*)(ab + k0);
        unsigned a1 = *(const unsigned*)(ab + k0 + 8*FS);
        unsigned a2 = *(const unsigned*)(ab + k0 + 8);
        unsigned a3 = *(const unsigned*)(ab + k0 + 8*FS + 8);
#pragma unroll
        for (int n = 0; n < 3; n++) {
            const __nv_bfloat16* bb = &sWf[(nw + n*8 + gr)*FS + k0 + qp];
            unsigned b0 = *(const unsigned*)bb;
            unsigned b1 = *(const unsigned*)(bb + 8);
            mma16816(acc[n], a0, a1, a2, a3, b0, b1);
        }
    }
    const int r0 = t0 + mw + gr;
#pragma unroll
    for (int n = 0; n < 3; n++) {
        int col = nw + n*8 + qp;
        float bb0 = sB[col], bb1 = sB[col + 1];
        float2 x0 = *(const float2*)&x[r0*96 + col];
        float2 x1 = *(const float2*)&x[(r0 + 8)*96 + col];
        *(float2*)&out[r0*96 + col] =
            make_float2(acc[n][0] + bb0 + x0.x, acc[n][1] + bb1 + x0.y);
        *(float2*)&out[(r0 + 8)*96 + col] =
            make_float2(acc[n][2] + bb0 + x1.x, acc[n][3] + bb1 + x1.y);
    }
}

// ---------------- launch -------------------------------------------------------
extern "C" void kernel_launch(void* const* d_in, const int* in_sizes, int n_in,
                              void* d_out, int out_size) {
    const float* x    = (const float*)d_in[0];
    const float* wqv  = (const float*)d_in[1];
    const float* wf   = (const float*)d_in[2];
    const int*   coo0 = (const int*)d_in[3];
    const int*   coo1 = (const int*)d_in[4];
    const int*   a2a  = (const int*)d_in[5];
    float*       out  = (float*)d_out;
    (void)in_sizes; (void)n_in; (void)out_size;

    const int smemA = (64*XS + 128*XS) * 2 + 128 * 4;        // 40448
    const int smemB = 4 * SPLH * sizeof(__half);             // 49152
    static int inited = 0;
    if (!inited) {
        cudaFuncSetAttribute(k_gemms, cudaFuncAttributeMaxDynamicSharedMemorySize, smemA);
        cudaFuncSetAttribute(k_attn,  cudaFuncAttributeMaxDynamicSharedMemorySize, smemB);
        inited = 1;
    }

    k_pre  <<<14, 256>>>(wqv, wf);
    k_gemms<<<459, 256, smemA>>>(x, coo0, coo1, a2a);
    k_attn <<<352, 256, smemB>>>(a2a);
    k_final<<<512, 256>>>(x, wf, out);
}